// round 13
// baseline (speedup 1.0000x reference)
#include <cuda_runtime.h>
#include <math.h>

#define NN 256
#define HH 256
#define DDE 64
#define NHD 4
#define CHUNK 32
#define NCHUNK 8
#define GH 260      // gh row stride (floats)
#define WGB 264     // WgB row stride (u32 bf16x2 per k-pair row)
#define QSB 36      // qsB row stride (u32 bf16x2 per j row)

typedef unsigned long long ull;

__device__ __forceinline__ ull pk2(float lo, float hi) {
    ull r; asm("mov.b64 %0,{%1,%2};" : "=l"(r) : "f"(lo), "f"(hi)); return r;
}
__device__ __forceinline__ float2 upk2(ull v) {
    float lo, hi; asm("mov.b64 {%0,%1},%2;" : "=f"(lo), "=f"(hi) : "l"(v));
    float2 f; f.x = lo; f.y = hi; return f;
}
__device__ __forceinline__ ull fma2_(ull a, ull b, ull c) {
    ull d; asm("fma.rn.f32x2 %0,%1,%2,%3;" : "=l"(d) : "l"(a), "l"(b), "l"(c)); return d;
}
__device__ __forceinline__ ull mul2_(ull a, ull b) {
    ull d; asm("mul.rn.f32x2 %0,%1,%2;" : "=l"(d) : "l"(a), "l"(b)); return d;
}
__device__ __forceinline__ float tanh_ap(float x) {
    float y; asm("tanh.approx.f32 %0,%1;" : "=f"(y) : "f"(x)); return y;
}
__device__ __forceinline__ float sig_ap(float x) {   // sigmoid via tanh
    return fmaf(tanh_ap(0.5f * x), 0.5f, 0.5f);
}
__device__ __forceinline__ unsigned bfx2(float lo, float hi) {
    unsigned r; asm("cvt.rn.bf16x2.f32 %0,%1,%2;" : "=r"(r) : "f"(hi), "f"(lo)); return r;
}
__device__ __forceinline__ void mma_bf16(float* c, const unsigned* a, const unsigned* b) {
    asm("mma.sync.aligned.m16n8k16.row.col.f32.bf16.bf16.f32 "
        "{%0,%1,%2,%3},{%4,%5,%6,%7},{%8,%9},{%0,%1,%2,%3};"
        : "+f"(c[0]), "+f"(c[1]), "+f"(c[2]), "+f"(c[3])
        : "r"(a[0]), "r"(a[1]), "r"(a[2]), "r"(a[3]), "r"(b[0]), "r"(b[1]));
}

// ---------------- device scratch ----------------
__device__ float g_PT[DDE * NN];
__device__ float g_C [NN * DDE];
__device__ float g_u [NHD * HH];
__device__ float g_v [NHD * HH];
__device__ float g_msm[NN * NHD * HH];

// ---------------- merged prep kernel (no tanh table) ----------------
// blocks 0..63: PT/C, block handles 4 j x 64 d
// blocks 64..191: u/v dot products, warp id = (bx-64)*8 + local warp
__global__ void prepK(const float* __restrict__ goal, const float* __restrict__ action,
                      const float* __restrict__ Wd, const float* __restrict__ bd,
                      const float* __restrict__ w, const float* __restrict__ a) {
    const int bx = blockIdx.x, t = threadIdx.x;
    if (bx < 64) {
        const int j = bx * 4 + (t >> 6), d = t & 63;
        const float a0 = action[j * 2 + 0], a1 = action[j * 2 + 1];
        const float go0 = goal[j * 2 + 0], go1 = goal[j * 2 + 1];
        g_PT[d * NN + j] = a0 * Wd[4 * DDE + d] + a1 * Wd[5 * DDE + d]
                         + go0 * Wd[6 * DDE + d] + go1 * Wd[7 * DDE + d];
        g_C[j * DDE + d] = a0 * Wd[0 * DDE + d] + a1 * Wd[1 * DDE + d]
                         + go0 * Wd[2 * DDE + d] + go1 * Wd[3 * DDE + d] + bd[d];
    } else {
        const int warp = (bx - 64) * 8 + (t >> 5);  // 0..1023 = z*256+h
        const int lane = t & 31;
        const float* row = w + warp * HH;
        float su = 0.f, sv = 0.f;
        #pragma unroll
        for (int f = lane; f < HH; f += 32) {
            const float wv = row[f];
            su = fmaf(wv, a[f], su);
            sv = fmaf(wv, a[HH + f], sv);
        }
        #pragma unroll
        for (int o = 16; o; o >>= 1) {
            su += __shfl_down_sync(0xffffffffu, su, o);
            sv += __shfl_down_sync(0xffffffffu, sv, o);
        }
        if (lane == 0) { g_u[warp] = su; g_v[warp] = sv; }
    }
}

// ---------------- main fused kernel: 256 thr, bf16 MMA, pipelined 2-barrier loop ----
#define SM_FLOATS (32 * WGB + 2 * CHUNK * GH + CHUNK * QSB + 1024 + 128 + 16 + 16)
#define SM_BYTES  (SM_FLOATS * 4)

__global__ void __launch_bounds__(256, 2) mainK(
    const float* __restrict__ ahs, const float* __restrict__ ghs,
    const float* __restrict__ Wg, const float* __restrict__ bg)
{
    extern __shared__ float sm[];
    unsigned* WgB = (unsigned*)sm;                     // [p=k/2][h] stride 264
    float* ghbuf  = sm + 32 * WGB;                     // 2 x [jl][h] stride 260
    unsigned* qsB = (unsigned*)(ghbuf + 2 * CHUNK * GH); // [jl][p] stride 36
    float* spp    = (float*)(qsB + CHUNK * QSB);       // [z][jl][w8] 1024
    float* psh    = spp + 1024;                        // [jl][z] 128
    float* bc     = psh + 128;                         // 16
    float* cvec   = bc + 16;                           // c1[0..3], s0[4..7]

    const int i    = blockIdx.x;
    const int tid  = threadIdx.x;
    const int lane = tid & 31;
    const int warp = tid >> 5;           // warp owns h in [warp*32, warp*32+32)
    const int g    = lane >> 2;          // groupID
    const int T    = lane & 3;           // threadID in group

    // Wg -> bf16x2 smem
    for (int k = tid; k < 32 * HH; k += 256) {
        const int p = k >> 8, h = k & 255;
        WgB[p * WGB + h] = bfx2(Wg[(2 * p) * HH + h], Wg[(2 * p + 1) * HH + h]);
    }

    // prologue dots: warp (z*2 + sel): c1 (u) / s0 (v)
    {
        const int z = warp >> 1;
        const float* src = (warp & 1) ? (g_v + z * HH) : (g_u + z * HH);
        float s = 0.f;
        #pragma unroll
        for (int h = lane; h < HH; h += 32) s = fmaf(ahs[i * HH + h], src[h], s);
        #pragma unroll
        for (int o = 16; o; o >>= 1) s += __shfl_xor_sync(0xffffffffu, s, o);
        if (lane == 0) cvec[(warp & 1) * 4 + z] = s;
    }

    // preload per-thread v pairs (4 heads x 4 ntiles) and gate-bias pairs
    float2 v2[NHD][4], bg2[4];
    #pragma unroll
    for (int nt = 0; nt < 4; nt++) {
        const int hb = warp * 32 + nt * 8 + 2 * T;
        bg2[nt] = *(const float2*)&bg[hb];
        #pragma unroll
        for (int z = 0; z < NHD; z++)
            v2[z][nt] = *(const float2*)&g_v[z * HH + hb];
    }

    const float ahs_i = ahs[i * HH + tid];

    // qsB prefill helper (parameterized thread range)
    auto prefill = [&](int jn0, int t0, int stride) {
        for (int idx = t0; idx < 32 * CHUNK; idx += stride) {
            const int p = idx >> 5, jj = idx & 31;
            const float v0 = fmaxf(g_C[i * DDE + 2 * p]     + g_PT[(2 * p) * NN + jn0 + jj], 0.f);
            const float v1 = fmaxf(g_C[i * DDE + 2 * p + 1] + g_PT[(2 * p + 1) * NN + jn0 + jj], 0.f);
            qsB[jj * QSB + p] = bfx2(v0, v1);
        }
    };

    // GEMM + epilogue for chunk cc, writing gh buffer gho and spp
    auto gemm_epi = [&](int cc, float* gho) {
        const int j0 = cc * CHUNK;
        // hoisted raw hidden-state loads (tanh applied inline; hide L2 under GEMM)
        float2 tj[4][4];
        #pragma unroll
        for (int mt = 0; mt < 2; mt++) {
            const int ja = j0 + mt * 16 + g, jb = ja + 8;
            #pragma unroll
            for (int nt = 0; nt < 4; nt++) {
                const int hb = warp * 32 + nt * 8 + 2 * T;
                tj[mt * 2 + 0][nt] = *(const float2*)&ahs[ja * HH + hb];
                tj[mt * 2 + 1][nt] = *(const float2*)&ahs[jb * HH + hb];
            }
        }
        float acc[2][4][4];
        #pragma unroll
        for (int mt = 0; mt < 2; mt++)
            #pragma unroll
            for (int nt = 0; nt < 4; nt++)
                #pragma unroll
                for (int e = 0; e < 4; e++) acc[mt][nt][e] = 0.f;
        #pragma unroll
        for (int kt = 0; kt < 4; kt++) {
            unsigned a[2][4], b[4][2];
            #pragma unroll
            for (int mt = 0; mt < 2; mt++) {
                const int ra = (mt * 16 + g) * QSB + kt * 8 + T;
                const int rb = ra + 8 * QSB;
                a[mt][0] = qsB[ra];
                a[mt][1] = qsB[rb];
                a[mt][2] = qsB[ra + 4];
                a[mt][3] = qsB[rb + 4];
            }
            #pragma unroll
            for (int nt = 0; nt < 4; nt++) {
                const int bi = (kt * 8 + T) * WGB + warp * 32 + nt * 8 + g;
                b[nt][0] = WgB[bi];
                b[nt][1] = WgB[bi + 4 * WGB];
            }
            #pragma unroll
            for (int mt = 0; mt < 2; mt++)
                #pragma unroll
                for (int nt = 0; nt < 4; nt++)
                    mma_bf16(acc[mt][nt], a[mt], b[nt]);
        }
        // epilogue: bias + sigmoid*tanh (diag override), store gh, fused scores
        float p[4][4];
        #pragma unroll
        for (int r = 0; r < 4; r++)
            #pragma unroll
            for (int z = 0; z < 4; z++) p[r][z] = 0.f;
        #pragma unroll
        for (int mt = 0; mt < 2; mt++) {
            const int ja = j0 + mt * 16 + g;
            const int jb = ja + 8;
            #pragma unroll
            for (int nt = 0; nt < 4; nt++) {
                const int hb = warp * 32 + nt * 8 + 2 * T;
                const float x00 = acc[mt][nt][0] + bg2[nt].x;
                const float x01 = acc[mt][nt][1] + bg2[nt].y;
                const float x10 = acc[mt][nt][2] + bg2[nt].x;
                const float x11 = acc[mt][nt][3] + bg2[nt].y;
                float2 gva, gvb;
                if (ja == i) {
                    gva = *(const float2*)&ghs[i * HH + hb];
                } else {
                    const float2 t = tj[mt * 2 + 0][nt];
                    gva.x = sig_ap(x00) * tanh_ap(t.x);
                    gva.y = sig_ap(x01) * tanh_ap(t.y);
                }
                if (jb == i) {
                    gvb = *(const float2*)&ghs[i * HH + hb];
                } else {
                    const float2 t = tj[mt * 2 + 1][nt];
                    gvb.x = sig_ap(x10) * tanh_ap(t.x);
                    gvb.y = sig_ap(x11) * tanh_ap(t.y);
                }
                *(float2*)&gho[(mt * 16 + g) * GH + hb]     = gva;
                *(float2*)&gho[(mt * 16 + g + 8) * GH + hb] = gvb;
                #pragma unroll
                for (int z = 0; z < 4; z++) {
                    p[mt * 2 + 0][z] = fmaf(gva.x, v2[z][nt].x,
                                       fmaf(gva.y, v2[z][nt].y, p[mt * 2 + 0][z]));
                    p[mt * 2 + 1][z] = fmaf(gvb.x, v2[z][nt].x,
                                       fmaf(gvb.y, v2[z][nt].y, p[mt * 2 + 1][z]));
                }
            }
        }
        #pragma unroll
        for (int r = 0; r < 4; r++)
            #pragma unroll
            for (int z = 0; z < 4; z++) {
                p[r][z] += __shfl_xor_sync(0xffffffffu, p[r][z], 1);
                p[r][z] += __shfl_xor_sync(0xffffffffu, p[r][z], 2);
            }
        #pragma unroll
        for (int r = 0; r < 4; r++)
            spp[T * 256 + (r * 8 + g) * 8 + warp] = p[r][T];
    };

    __syncthreads();   // WgB + cvec ready

    // online-softmax state (replicated across threads)
    float runmax0, runmax1, runmax2, runmax3;
    float denom0 = 1.f, denom1 = 1.f, denom2 = 1.f, denom3 = 1.f;
    {
        const float s0v = cvec[0] + cvec[4], s1v = cvec[1] + cvec[5];
        const float s2v = cvec[2] + cvec[6], s3v = cvec[3] + cvec[7];
        runmax0 = (s0v > 0.f) ? s0v : 0.2f * s0v;
        runmax1 = (s1v > 0.f) ? s1v : 0.2f * s1v;
        runmax2 = (s2v > 0.f) ? s2v : 0.2f * s2v;
        runmax3 = (s3v > 0.f) ? s3v : 0.2f * s3v;
    }
    ull mA = pk2(ahs_i, ahs_i), mB = mA;   // (m0,m1),(m2,m3)

    // prologue: chunk 0 qs + GEMM/epilogue
    prefill(0, tid, 256);
    __syncthreads();
    gemm_epi(0, ghbuf);
    __syncthreads();   // A(0): gh[0] + spp(0) ready

    for (int c = 0; c < NCHUNK; c++) {
        // ---- phase 1: warps 0-3 softmax(c); warps 4-7 prefill qsB(c+1) ----
        if (warp < 4) {
            float e = cvec[warp];
            #pragma unroll
            for (int w8 = 0; w8 < 8; w8++) e += spp[warp * 256 + lane * 8 + w8];
            e = (e > 0.f) ? e : 0.2f * e;
            const float rmz = (warp == 0) ? runmax0 : (warp == 1) ? runmax1
                            : (warp == 2) ? runmax2 : runmax3;
            float mx = e;
            #pragma unroll
            for (int o = 16; o; o >>= 1) mx = fmaxf(mx, __shfl_xor_sync(0xffffffffu, mx, o));
            const float nm = fmaxf(rmz, mx);
            const float pp = __expf(e - nm);
            psh[lane * 4 + warp] = pp;
            float ps = pp;
            #pragma unroll
            for (int o = 16; o; o >>= 1) ps += __shfl_xor_sync(0xffffffffu, ps, o);
            if (lane == 0) { bc[warp] = mx; bc[4 + warp] = ps; }
        } else if (c + 1 < NCHUNK) {
            prefill((c + 1) * CHUNK, tid - 128, 128);
        }
        __syncthreads();   // B: psh + bc + next qsB ready

        // ---- phase 2: GEMM/epilogue(c+1) first (long chains), then merge + m-accum(c) ----
        if (c + 1 < NCHUNK)
            gemm_epi(c + 1, ghbuf + ((c + 1) & 1) * CHUNK * GH);
        {
            const float nm0 = fmaxf(runmax0, bc[0]);
            const float nm1 = fmaxf(runmax1, bc[1]);
            const float nm2 = fmaxf(runmax2, bc[2]);
            const float nm3 = fmaxf(runmax3, bc[3]);
            const float s0 = __expf(runmax0 - nm0), s1 = __expf(runmax1 - nm1);
            const float s2 = __expf(runmax2 - nm2), s3 = __expf(runmax3 - nm3);
            denom0 = denom0 * s0 + bc[4]; denom1 = denom1 * s1 + bc[5];
            denom2 = denom2 * s2 + bc[6]; denom3 = denom3 * s3 + bc[7];
            runmax0 = nm0; runmax1 = nm1; runmax2 = nm2; runmax3 = nm3;
            mA = mul2_(mA, pk2(s0, s1));
            mB = mul2_(mB, pk2(s2, s3));
        }
        {
            const float* ghc = ghbuf + (c & 1) * CHUNK * GH;
            #pragma unroll 4
            for (int jj = 0; jj < CHUNK; jj++) {
                const float ghv = ghc[jj * GH + tid];
                const ulonglong2 pp = *(const ulonglong2*)&psh[jj * 4];
                const ull gd = pk2(ghv, ghv);
                mA = fma2_(pp.x, gd, mA);
                mB = fma2_(pp.y, gd, mB);
            }
        }
        if (c + 1 < NCHUNK)
            __syncthreads();   // A(c+1): gh[(c+1)&1] + spp(c+1) ready
    }

    // write normalized m: g_msm[i][z*256 + h]
    {
        const float2 fA = upk2(mA), fB = upk2(mB);
        g_msm[i * (NHD * HH) + 0 * HH + tid] = fA.x / denom0;
        g_msm[i * (NHD * HH) + 1 * HH + tid] = fA.y / denom1;
        g_msm[i * (NHD * HH) + 2 * HH + tid] = fB.x / denom2;
        g_msm[i * (NHD * HH) + 3 * HH + tid] = fB.y / denom3;
    }
}

// ---------------- projection kernel: coalesced float4 gather, 512 threads ----------------
__global__ void __launch_bounds__(512) projK(const float* __restrict__ w,
                                             const float* __restrict__ bias,
                                             float* __restrict__ out) {
    __shared__ float msm_s[8192];   // [k][n], n contiguous (8)
    __shared__ float sacc[4096];    // [kw(16)][n(8)][fl(32)]
    const int tid = threadIdx.x;
    const int f0 = (blockIdx.x & 7) * 32;
    const int n0 = (blockIdx.x >> 3) * 8;

    // coalesced float4: consecutive threads read consecutive k-quads of one n row
    for (int idx = tid; idx < 2048; idx += 512) {
        const int n = idx >> 8, k4 = idx & 255;
        const float4 v = *(const float4*)&g_msm[(n0 + n) * 1024 + k4 * 4];
        msm_s[(k4 * 4 + 0) * 8 + n] = v.x;
        msm_s[(k4 * 4 + 1) * 8 + n] = v.y;
        msm_s[(k4 * 4 + 2) * 8 + n] = v.z;
        msm_s[(k4 * 4 + 3) * 8 + n] = v.w;
    }
    __syncthreads();

    const int fl = tid & 31, kw = tid >> 5;   // kw 0..15
    float acc[8] = {0.f, 0.f, 0.f, 0.f, 0.f, 0.f, 0.f, 0.f};
    const float* wp = w + f0 + fl;
    const int kbeg = kw * 64;
    #pragma unroll 8
    for (int k = kbeg; k < kbeg + 64; k++) {
        const float wv = wp[k * 256];
        const float4 ma = *(const float4*)&msm_s[k * 8];
        const float4 mb = *(const float4*)&msm_s[k * 8 + 4];
        acc[0] = fmaf(wv, ma.x, acc[0]); acc[1] = fmaf(wv, ma.y, acc[1]);
        acc[2] = fmaf(wv, ma.z, acc[2]); acc[3] = fmaf(wv, ma.w, acc[3]);
        acc[4] = fmaf(wv, mb.x, acc[4]); acc[5] = fmaf(wv, mb.y, acc[5]);
        acc[6] = fmaf(wv, mb.z, acc[6]); acc[7] = fmaf(wv, mb.w, acc[7]);
    }
    #pragma unroll
    for (int n = 0; n < 8; n++) sacc[(kw * 8 + n) * 32 + fl] = acc[n];
    __syncthreads();

    if (tid < 256) {
        const int n = tid >> 5;
        float s = 0.f;
        #pragma unroll
        for (int k2 = 0; k2 < 16; k2++) s += sacc[(k2 * 8 + n) * 32 + fl];
        out[(n0 + n) * 256 + f0 + fl] = fmaxf(0.25f * s, 0.f) + bias[f0 + fl];
    }
}

// ---------------- launch ----------------
extern "C" void kernel_launch(void* const* d_in, const int* in_sizes, int n_in,
                              void* d_out, int out_size) {
    (void)in_sizes; (void)n_in; (void)out_size;
    const float* ahs    = (const float*)d_in[0];
    const float* ghs    = (const float*)d_in[1];
    const float* goal   = (const float*)d_in[2];
    const float* action = (const float*)d_in[3];
    const float* Wd     = (const float*)d_in[4];
    const float* bd     = (const float*)d_in[5];
    const float* Wg     = (const float*)d_in[6];
    const float* bg     = (const float*)d_in[7];
    const float* w      = (const float*)d_in[8];
    const float* a      = (const float*)d_in[9];
    const float* bias   = (const float*)d_in[10];
    float* out = (float*)d_out;

    cudaFuncSetAttribute(mainK, cudaFuncAttributeMaxDynamicSharedMemorySize, SM_BYTES);

    prepK<<<192, 256>>>(goal, action, Wd, bd, w, a);
    mainK<<<NN, 256, SM_BYTES>>>(ahs, ghs, Wg, bg);
    projK<<<NN, 512>>>(w, bias, out);
}

// round 14
// speedup vs baseline: 1.2490x; 1.2490x over previous
#include <cuda_runtime.h>
#include <math.h>

#define NN 256
#define HH 256
#define DDE 64
#define NHD 4
#define CHUNK 32
#define NCHUNK 8
#define GH 260      // gh row stride (floats)
#define WGB 264     // WgB row stride (u32 bf16x2 per k-pair row)
#define QSB 36      // qsB row stride (u32 bf16x2 per j row)

typedef unsigned long long ull;

__device__ __forceinline__ ull pk2(float lo, float hi) {
    ull r; asm("mov.b64 %0,{%1,%2};" : "=l"(r) : "f"(lo), "f"(hi)); return r;
}
__device__ __forceinline__ float2 upk2(ull v) {
    float lo, hi; asm("mov.b64 {%0,%1},%2;" : "=f"(lo), "=f"(hi) : "l"(v));
    float2 f; f.x = lo; f.y = hi; return f;
}
__device__ __forceinline__ ull fma2_(ull a, ull b, ull c) {
    ull d; asm("fma.rn.f32x2 %0,%1,%2,%3;" : "=l"(d) : "l"(a), "l"(b), "l"(c)); return d;
}
__device__ __forceinline__ ull mul2_(ull a, ull b) {
    ull d; asm("mul.rn.f32x2 %0,%1,%2;" : "=l"(d) : "l"(a), "l"(b)); return d;
}
__device__ __forceinline__ float tanh_ap(float x) {
    float y; asm("tanh.approx.f32 %0,%1;" : "=f"(y) : "f"(x)); return y;
}
__device__ __forceinline__ float sig_ap(float x) {   // sigmoid via tanh
    return fmaf(tanh_ap(0.5f * x), 0.5f, 0.5f);
}
__device__ __forceinline__ unsigned bfx2(float lo, float hi) {
    unsigned r; asm("cvt.rn.bf16x2.f32 %0,%1,%2;" : "=r"(r) : "f"(hi), "f"(lo)); return r;
}
__device__ __forceinline__ void mma_bf16(float* c, const unsigned* a, const unsigned* b) {
    asm("mma.sync.aligned.m16n8k16.row.col.f32.bf16.bf16.f32 "
        "{%0,%1,%2,%3},{%4,%5,%6,%7},{%8,%9},{%0,%1,%2,%3};"
        : "+f"(c[0]), "+f"(c[1]), "+f"(c[2]), "+f"(c[3])
        : "r"(a[0]), "r"(a[1]), "r"(a[2]), "r"(a[3]), "r"(b[0]), "r"(b[1]));
}

// ---------------- device scratch ----------------
__device__ float g_tTj[NN * HH];   // tanh(ahs[j,h])
__device__ float g_PT[DDE * NN];
__device__ float g_C [NN * DDE];
__device__ float g_u [NHD * HH];
__device__ float g_v [NHD * HH];
__device__ float g_msm[NN * NHD * HH];

// ---------------- merged prep kernel ----------------
__global__ void prepK(const float* __restrict__ ahs, const float* __restrict__ goal,
                      const float* __restrict__ action, const float* __restrict__ Wd,
                      const float* __restrict__ bd, const float* __restrict__ w,
                      const float* __restrict__ a) {
    const int bx = blockIdx.x, t = threadIdx.x;
    if (bx < NN) {
        const int j = bx;
        g_tTj[j * HH + t] = tanhf(ahs[j * HH + t]);
        if (t < DDE) {
            const float a0 = action[j * 2 + 0], a1 = action[j * 2 + 1];
            const float go0 = goal[j * 2 + 0], go1 = goal[j * 2 + 1];
            g_PT[t * NN + j] = a0 * Wd[4 * DDE + t] + a1 * Wd[5 * DDE + t]
                             + go0 * Wd[6 * DDE + t] + go1 * Wd[7 * DDE + t];
            g_C[j * DDE + t] = a0 * Wd[0 * DDE + t] + a1 * Wd[1 * DDE + t]
                             + go0 * Wd[2 * DDE + t] + go1 * Wd[3 * DDE + t] + bd[t];
        }
    } else {
        const int warp = (bx - NN) * 8 + (t >> 5);  // 0..1023 = z*256+h
        const int lane = t & 31;
        const float* row = w + warp * HH;
        float su = 0.f, sv = 0.f;
        #pragma unroll
        for (int f = lane; f < HH; f += 32) {
            const float wv = row[f];
            su = fmaf(wv, a[f], su);
            sv = fmaf(wv, a[HH + f], sv);
        }
        #pragma unroll
        for (int o = 16; o; o >>= 1) {
            su += __shfl_down_sync(0xffffffffu, su, o);
            sv += __shfl_down_sync(0xffffffffu, sv, o);
        }
        if (lane == 0) { g_u[warp] = su; g_v[warp] = sv; }
    }
}

// ---------------- main fused kernel: 256 thr, bf16 MMA, pipelined 2-barrier loop ----
#define SM_FLOATS (32 * WGB + 2 * CHUNK * GH + CHUNK * QSB + 1024 + 128 + 16 + 16)
#define SM_BYTES  (SM_FLOATS * 4)

__global__ void __launch_bounds__(256, 2) mainK(
    const float* __restrict__ ahs, const float* __restrict__ ghs,
    const float* __restrict__ Wg, const float* __restrict__ bg)
{
    extern __shared__ float sm[];
    unsigned* WgB = (unsigned*)sm;                     // [p=k/2][h] stride 264
    float* ghbuf  = sm + 32 * WGB;                     // 2 x [jl][h] stride 260
    unsigned* qsB = (unsigned*)(ghbuf + 2 * CHUNK * GH); // [jl][p] stride 36
    float* spp    = (float*)(qsB + CHUNK * QSB);       // [z][jl][w8] 1024
    float* psh    = spp + 1024;                        // [jl][z] 128
    float* bc     = psh + 128;                         // 16
    float* cvec   = bc + 16;                           // c1[0..3], s0[4..7]

    const int i    = blockIdx.x;
    const int tid  = threadIdx.x;
    const int lane = tid & 31;
    const int warp = tid >> 5;           // warp owns h in [warp*32, warp*32+32)
    const int g    = lane >> 2;          // groupID
    const int T    = lane & 3;           // threadID in group

    // Wg -> bf16x2 smem
    for (int k = tid; k < 32 * HH; k += 256) {
        const int p = k >> 8, h = k & 255;
        WgB[p * WGB + h] = bfx2(Wg[(2 * p) * HH + h], Wg[(2 * p + 1) * HH + h]);
    }

    // prologue dots: warp (z*2 + sel): c1 (u) / s0 (v)
    {
        const int z = warp >> 1;
        const float* src = (warp & 1) ? (g_v + z * HH) : (g_u + z * HH);
        float s = 0.f;
        #pragma unroll
        for (int h = lane; h < HH; h += 32) s = fmaf(ahs[i * HH + h], src[h], s);
        #pragma unroll
        for (int o = 16; o; o >>= 1) s += __shfl_xor_sync(0xffffffffu, s, o);
        if (lane == 0) cvec[(warp & 1) * 4 + z] = s;
    }

    // preload per-thread v pairs (4 heads x 4 ntiles) and gate-bias pairs
    float2 v2[NHD][4], bg2[4];
    #pragma unroll
    for (int nt = 0; nt < 4; nt++) {
        const int hb = warp * 32 + nt * 8 + 2 * T;
        bg2[nt] = *(const float2*)&bg[hb];
        #pragma unroll
        for (int z = 0; z < NHD; z++)
            v2[z][nt] = *(const float2*)&g_v[z * HH + hb];
    }

    const float ahs_i = ahs[i * HH + tid];

    // qsB prefill helper (parameterized thread range)
    auto prefill = [&](int jn0, int t0, int stride) {
        for (int idx = t0; idx < 32 * CHUNK; idx += stride) {
            const int p = idx >> 5, jj = idx & 31;
            const float v0 = fmaxf(g_C[i * DDE + 2 * p]     + g_PT[(2 * p) * NN + jn0 + jj], 0.f);
            const float v1 = fmaxf(g_C[i * DDE + 2 * p + 1] + g_PT[(2 * p + 1) * NN + jn0 + jj], 0.f);
            qsB[jj * QSB + p] = bfx2(v0, v1);
        }
    };

    // GEMM + epilogue for chunk cc, writing gh buffer gho and spp
    auto gemm_epi = [&](int cc, float* gho) {
        const int j0 = cc * CHUNK;
        // hoisted tanh-table loads (hide L2 under GEMM)
        float2 tj[4][4];
        #pragma unroll
        for (int mt = 0; mt < 2; mt++) {
            const int ja = j0 + mt * 16 + g, jb = ja + 8;
            #pragma unroll
            for (int nt = 0; nt < 4; nt++) {
                const int hb = warp * 32 + nt * 8 + 2 * T;
                tj[mt * 2 + 0][nt] = *(const float2*)&g_tTj[ja * HH + hb];
                tj[mt * 2 + 1][nt] = *(const float2*)&g_tTj[jb * HH + hb];
            }
        }
        float acc[2][4][4];
        #pragma unroll
        for (int mt = 0; mt < 2; mt++)
            #pragma unroll
            for (int nt = 0; nt < 4; nt++)
                #pragma unroll
                for (int e = 0; e < 4; e++) acc[mt][nt][e] = 0.f;
        #pragma unroll
        for (int kt = 0; kt < 4; kt++) {
            unsigned a[2][4], b[4][2];
            #pragma unroll
            for (int mt = 0; mt < 2; mt++) {
                const int ra = (mt * 16 + g) * QSB + kt * 8 + T;
                const int rb = ra + 8 * QSB;
                a[mt][0] = qsB[ra];
                a[mt][1] = qsB[rb];
                a[mt][2] = qsB[ra + 4];
                a[mt][3] = qsB[rb + 4];
            }
            #pragma unroll
            for (int nt = 0; nt < 4; nt++) {
                const int bi = (kt * 8 + T) * WGB + warp * 32 + nt * 8 + g;
                b[nt][0] = WgB[bi];
                b[nt][1] = WgB[bi + 4 * WGB];
            }
            #pragma unroll
            for (int mt = 0; mt < 2; mt++)
                #pragma unroll
                for (int nt = 0; nt < 4; nt++)
                    mma_bf16(acc[mt][nt], a[mt], b[nt]);
        }
        // epilogue: bias + sigmoid*tanh (diag override), store gh, fused scores
        float p[4][4];
        #pragma unroll
        for (int r = 0; r < 4; r++)
            #pragma unroll
            for (int z = 0; z < 4; z++) p[r][z] = 0.f;
        #pragma unroll
        for (int mt = 0; mt < 2; mt++) {
            const int ja = j0 + mt * 16 + g;
            const int jb = ja + 8;
            #pragma unroll
            for (int nt = 0; nt < 4; nt++) {
                const int hb = warp * 32 + nt * 8 + 2 * T;
                const float x00 = acc[mt][nt][0] + bg2[nt].x;
                const float x01 = acc[mt][nt][1] + bg2[nt].y;
                const float x10 = acc[mt][nt][2] + bg2[nt].x;
                const float x11 = acc[mt][nt][3] + bg2[nt].y;
                float2 gva, gvb;
                if (ja == i) {
                    gva = *(const float2*)&ghs[i * HH + hb];
                } else {
                    const float2 t = tj[mt * 2 + 0][nt];
                    gva.x = sig_ap(x00) * t.x;
                    gva.y = sig_ap(x01) * t.y;
                }
                if (jb == i) {
                    gvb = *(const float2*)&ghs[i * HH + hb];
                } else {
                    const float2 t = tj[mt * 2 + 1][nt];
                    gvb.x = sig_ap(x10) * t.x;
                    gvb.y = sig_ap(x11) * t.y;
                }
                *(float2*)&gho[(mt * 16 + g) * GH + hb]     = gva;
                *(float2*)&gho[(mt * 16 + g + 8) * GH + hb] = gvb;
                #pragma unroll
                for (int z = 0; z < 4; z++) {
                    p[mt * 2 + 0][z] = fmaf(gva.x, v2[z][nt].x,
                                       fmaf(gva.y, v2[z][nt].y, p[mt * 2 + 0][z]));
                    p[mt * 2 + 1][z] = fmaf(gvb.x, v2[z][nt].x,
                                       fmaf(gvb.y, v2[z][nt].y, p[mt * 2 + 1][z]));
                }
            }
        }
        // transpose-reduce over the quad: lane T ends with sum_{quad} p[r][z=T]
        const bool t1 = (T & 1), t2 = (T & 2);
        #pragma unroll
        for (int r = 0; r < 4; r++) {
            float k0 = t1 ? p[r][1] : p[r][0];
            float s0 = t1 ? p[r][0] : p[r][1];
            float k2 = t1 ? p[r][3] : p[r][2];
            float s2 = t1 ? p[r][2] : p[r][3];
            k0 += __shfl_xor_sync(0xffffffffu, s0, 1);
            k2 += __shfl_xor_sync(0xffffffffu, s2, 1);
            float kk = t2 ? k2 : k0;
            float ss = t2 ? k0 : k2;
            kk += __shfl_xor_sync(0xffffffffu, ss, 2);
            spp[T * 256 + (r * 8 + g) * 8 + warp] = kk;
        }
    };

    __syncthreads();   // WgB + cvec ready

    // online-softmax state (replicated across threads)
    float runmax0, runmax1, runmax2, runmax3;
    float denom0 = 1.f, denom1 = 1.f, denom2 = 1.f, denom3 = 1.f;
    {
        const float s0v = cvec[0] + cvec[4], s1v = cvec[1] + cvec[5];
        const float s2v = cvec[2] + cvec[6], s3v = cvec[3] + cvec[7];
        runmax0 = (s0v > 0.f) ? s0v : 0.2f * s0v;
        runmax1 = (s1v > 0.f) ? s1v : 0.2f * s1v;
        runmax2 = (s2v > 0.f) ? s2v : 0.2f * s2v;
        runmax3 = (s3v > 0.f) ? s3v : 0.2f * s3v;
    }
    ull mA = pk2(ahs_i, ahs_i), mB = mA;   // (m0,m1),(m2,m3)

    // prologue: chunk 0 qs + GEMM/epilogue
    prefill(0, tid, 256);
    __syncthreads();
    gemm_epi(0, ghbuf);
    __syncthreads();   // A(0): gh[0] + spp(0) ready

    for (int c = 0; c < NCHUNK; c++) {
        // ---- phase 1: warps 0-3 softmax(c); warps 4-7 prefill qsB(c+1) ----
        if (warp < 4) {
            float e = cvec[warp];
            #pragma unroll
            for (int w8 = 0; w8 < 8; w8++) e += spp[warp * 256 + lane * 8 + w8];
            e = (e > 0.f) ? e : 0.2f * e;
            const float rmz = (warp == 0) ? runmax0 : (warp == 1) ? runmax1
                            : (warp == 2) ? runmax2 : runmax3;
            float mx = e;
            #pragma unroll
            for (int o = 16; o; o >>= 1) mx = fmaxf(mx, __shfl_xor_sync(0xffffffffu, mx, o));
            const float nm = fmaxf(rmz, mx);
            const float pp = __expf(e - nm);
            psh[lane * 4 + warp] = pp;
            float ps = pp;
            #pragma unroll
            for (int o = 16; o; o >>= 1) ps += __shfl_xor_sync(0xffffffffu, ps, o);
            if (lane == 0) { bc[warp] = mx; bc[4 + warp] = ps; }
        } else if (c + 1 < NCHUNK) {
            prefill((c + 1) * CHUNK, tid - 128, 128);
        }
        __syncthreads();   // B: psh + bc + next qsB ready

        // ---- phase 2: merge state + m-accum(c), then GEMM/epilogue(c+1) ----
        {
            const float nm0 = fmaxf(runmax0, bc[0]);
            const float nm1 = fmaxf(runmax1, bc[1]);
            const float nm2 = fmaxf(runmax2, bc[2]);
            const float nm3 = fmaxf(runmax3, bc[3]);
            const float s0 = __expf(runmax0 - nm0), s1 = __expf(runmax1 - nm1);
            const float s2 = __expf(runmax2 - nm2), s3 = __expf(runmax3 - nm3);
            denom0 = denom0 * s0 + bc[4]; denom1 = denom1 * s1 + bc[5];
            denom2 = denom2 * s2 + bc[6]; denom3 = denom3 * s3 + bc[7];
            runmax0 = nm0; runmax1 = nm1; runmax2 = nm2; runmax3 = nm3;
            mA = mul2_(mA, pk2(s0, s1));
            mB = mul2_(mB, pk2(s2, s3));
        }
        {
            const float* ghc = ghbuf + (c & 1) * CHUNK * GH;
            #pragma unroll 4
            for (int jj = 0; jj < CHUNK; jj++) {
                const float ghv = ghc[jj * GH + tid];
                const ulonglong2 pp = *(const ulonglong2*)&psh[jj * 4];
                const ull gd = pk2(ghv, ghv);
                mA = fma2_(pp.x, gd, mA);
                mB = fma2_(pp.y, gd, mB);
            }
        }
        if (c + 1 < NCHUNK) {
            gemm_epi(c + 1, ghbuf + ((c + 1) & 1) * CHUNK * GH);
            __syncthreads();   // A(c+1): gh[(c+1)&1] + spp(c+1) ready
        }
    }

    // write normalized m: g_msm[i][z*256 + h]
    {
        const float2 fA = upk2(mA), fB = upk2(mB);
        g_msm[i * (NHD * HH) + 0 * HH + tid] = fA.x / denom0;
        g_msm[i * (NHD * HH) + 1 * HH + tid] = fA.y / denom1;
        g_msm[i * (NHD * HH) + 2 * HH + tid] = fB.x / denom2;
        g_msm[i * (NHD * HH) + 3 * HH + tid] = fB.y / denom3;
    }
}

// ---------------- projection kernel: coalesced gather, 512 threads ----------------
__global__ void __launch_bounds__(512) projK(const float* __restrict__ w,
                                             const float* __restrict__ bias,
                                             float* __restrict__ out) {
    __shared__ float msm_s[8192];   // [k][n], n contiguous (8)
    __shared__ float sacc[4096];    // [kw(16)][n(8)][fl(32)]
    const int tid = threadIdx.x;
    const int f0 = (blockIdx.x & 7) * 32;
    const int n0 = (blockIdx.x >> 3) * 8;

    // coalesced: consecutive threads read consecutive k of the same n row
    for (int idx = tid; idx < 8192; idx += 512) {
        const int n = idx >> 10, k = idx & 1023;
        msm_s[k * 8 + n] = g_msm[(n0 + n) * 1024 + k];
    }
    __syncthreads();

    const int fl = tid & 31, kw = tid >> 5;   // kw 0..15
    float acc[8] = {0.f, 0.f, 0.f, 0.f, 0.f, 0.f, 0.f, 0.f};
    const float* wp = w + f0 + fl;
    const int kbeg = kw * 64;
    #pragma unroll 8
    for (int k = kbeg; k < kbeg + 64; k++) {
        const float wv = wp[k * 256];
        const float4 ma = *(const float4*)&msm_s[k * 8];
        const float4 mb = *(const float4*)&msm_s[k * 8 + 4];
        acc[0] = fmaf(wv, ma.x, acc[0]); acc[1] = fmaf(wv, ma.y, acc[1]);
        acc[2] = fmaf(wv, ma.z, acc[2]); acc[3] = fmaf(wv, ma.w, acc[3]);
        acc[4] = fmaf(wv, mb.x, acc[4]); acc[5] = fmaf(wv, mb.y, acc[5]);
        acc[6] = fmaf(wv, mb.z, acc[6]); acc[7] = fmaf(wv, mb.w, acc[7]);
    }
    #pragma unroll
    for (int n = 0; n < 8; n++) sacc[(kw * 8 + n) * 32 + fl] = acc[n];
    __syncthreads();

    if (tid < 256) {
        const int n = tid >> 5;
        float s = 0.f;
        #pragma unroll
        for (int k2 = 0; k2 < 16; k2++) s += sacc[(k2 * 8 + n) * 32 + fl];
        out[(n0 + n) * 256 + f0 + fl] = fmaxf(0.25f * s, 0.f) + bias[f0 + fl];
    }
}

// ---------------- launch ----------------
extern "C" void kernel_launch(void* const* d_in, const int* in_sizes, int n_in,
                              void* d_out, int out_size) {
    (void)in_sizes; (void)n_in; (void)out_size;
    const float* ahs    = (const float*)d_in[0];
    const float* ghs    = (const float*)d_in[1];
    const float* goal   = (const float*)d_in[2];
    const float* action = (const float*)d_in[3];
    const float* Wd     = (const float*)d_in[4];
    const float* bd     = (const float*)d_in[5];
    const float* Wg     = (const float*)d_in[6];
    const float* bg     = (const float*)d_in[7];
    const float* w      = (const float*)d_in[8];
    const float* a      = (const float*)d_in[9];
    const float* bias   = (const float*)d_in[10];
    float* out = (float*)d_out;

    cudaFuncSetAttribute(mainK, cudaFuncAttributeMaxDynamicSharedMemorySize, SM_BYTES);

    prepK<<<NN + 128, 256>>>(ahs, goal, action, Wd, bd, w, a);
    mainK<<<NN, 256, SM_BYTES>>>(ahs, ghs, Wg, bg);
    projK<<<NN, 512>>>(w, bias, out);
}

// round 15
// speedup vs baseline: 1.2588x; 1.0078x over previous
#include <cuda_runtime.h>
#include <math.h>

#define NN 256
#define HH 256
#define DDE 64
#define NHD 4
#define CHUNK 32
#define NCHUNK 8
#define GH 260      // gh row stride (floats)
#define WGB 264     // WgB row stride (u32 bf16x2 per k-pair row)
#define QSB 36      // qsB row stride (u32 bf16x2 per j row)

typedef unsigned long long ull;

__device__ __forceinline__ ull pk2(float lo, float hi) {
    ull r; asm("mov.b64 %0,{%1,%2};" : "=l"(r) : "f"(lo), "f"(hi)); return r;
}
__device__ __forceinline__ float2 upk2(ull v) {
    float lo, hi; asm("mov.b64 {%0,%1},%2;" : "=f"(lo), "=f"(hi) : "l"(v));
    float2 f; f.x = lo; f.y = hi; return f;
}
__device__ __forceinline__ ull fma2_(ull a, ull b, ull c) {
    ull d; asm("fma.rn.f32x2 %0,%1,%2,%3;" : "=l"(d) : "l"(a), "l"(b), "l"(c)); return d;
}
__device__ __forceinline__ ull mul2_(ull a, ull b) {
    ull d; asm("mul.rn.f32x2 %0,%1,%2;" : "=l"(d) : "l"(a), "l"(b)); return d;
}
__device__ __forceinline__ float tanh_ap(float x) {
    float y; asm("tanh.approx.f32 %0,%1;" : "=f"(y) : "f"(x)); return y;
}
__device__ __forceinline__ float sig_ap(float x) {   // sigmoid via tanh
    return fmaf(tanh_ap(0.5f * x), 0.5f, 0.5f);
}
__device__ __forceinline__ unsigned bfx2(float lo, float hi) {
    unsigned r; asm("cvt.rn.bf16x2.f32 %0,%1,%2;" : "=r"(r) : "f"(hi), "f"(lo)); return r;
}
__device__ __forceinline__ void mma_bf16(float* c, const unsigned* a, const unsigned* b) {
    asm("mma.sync.aligned.m16n8k16.row.col.f32.bf16.bf16.f32 "
        "{%0,%1,%2,%3},{%4,%5,%6,%7},{%8,%9},{%0,%1,%2,%3};"
        : "+f"(c[0]), "+f"(c[1]), "+f"(c[2]), "+f"(c[3])
        : "r"(a[0]), "r"(a[1]), "r"(a[2]), "r"(a[3]), "r"(b[0]), "r"(b[1]));
}

// ---------------- device scratch ----------------
__device__ float g_tTj[NN * HH];   // tanh(ahs[j,h])
__device__ float g_PT[DDE * NN];
__device__ float g_C [NN * DDE];
__device__ float g_u [NHD * HH];
__device__ float g_v [NHD * HH];
__device__ float g_msm[NN * NHD * HH];

// ---------------- merged prep kernel ----------------
__global__ void prepK(const float* __restrict__ ahs, const float* __restrict__ goal,
                      const float* __restrict__ action, const float* __restrict__ Wd,
                      const float* __restrict__ bd, const float* __restrict__ w,
                      const float* __restrict__ a) {
    const int bx = blockIdx.x, t = threadIdx.x;
    if (bx < NN) {
        const int j = bx;
        g_tTj[j * HH + t] = tanhf(ahs[j * HH + t]);
        if (t < DDE) {
            const float a0 = action[j * 2 + 0], a1 = action[j * 2 + 1];
            const float go0 = goal[j * 2 + 0], go1 = goal[j * 2 + 1];
            g_PT[t * NN + j] = a0 * Wd[4 * DDE + t] + a1 * Wd[5 * DDE + t]
                             + go0 * Wd[6 * DDE + t] + go1 * Wd[7 * DDE + t];
            g_C[j * DDE + t] = a0 * Wd[0 * DDE + t] + a1 * Wd[1 * DDE + t]
                             + go0 * Wd[2 * DDE + t] + go1 * Wd[3 * DDE + t] + bd[t];
        }
    } else {
        const int warp = (bx - NN) * 8 + (t >> 5);  // 0..1023 = z*256+h
        const int lane = t & 31;
        const float* row = w + warp * HH;
        float su = 0.f, sv = 0.f;
        #pragma unroll
        for (int f = lane; f < HH; f += 32) {
            const float wv = row[f];
            su = fmaf(wv, a[f], su);
            sv = fmaf(wv, a[HH + f], sv);
        }
        #pragma unroll
        for (int o = 16; o; o >>= 1) {
            su += __shfl_down_sync(0xffffffffu, su, o);
            sv += __shfl_down_sync(0xffffffffu, sv, o);
        }
        if (lane == 0) { g_u[warp] = su; g_v[warp] = sv; }
    }
}

// ---------------- main fused kernel: 256 thr, bf16 MMA, pipelined 2-barrier loop ----
#define SM_FLOATS (32 * WGB + 2 * CHUNK * GH + CHUNK * QSB + 1024 + 128 + 16 + 16)
#define SM_BYTES  (SM_FLOATS * 4)

__global__ void __launch_bounds__(256, 2) mainK(
    const float* __restrict__ ahs, const float* __restrict__ ghs,
    const float* __restrict__ Wg, const float* __restrict__ bg)
{
    extern __shared__ float sm[];
    unsigned* WgB = (unsigned*)sm;                     // [p=k/2][h] stride 264
    float* ghbuf  = sm + 32 * WGB;                     // 2 x [jl][h] stride 260
    unsigned* qsB = (unsigned*)(ghbuf + 2 * CHUNK * GH); // [jl][p] stride 36
    float* spp    = (float*)(qsB + CHUNK * QSB);       // [z][jl][w8] 1024
    float* psh    = spp + 1024;                        // [jl][z] 128
    float* bc     = psh + 128;                         // 16
    float* cvec   = bc + 16;                           // c1[0..3], s0[4..7]

    const int i    = blockIdx.x;
    const int tid  = threadIdx.x;
    const int lane = tid & 31;
    const int warp = tid >> 5;           // warp owns h in [warp*32, warp*32+32)
    const int g    = lane >> 2;          // groupID
    const int T    = lane & 3;           // threadID in group

    // Wg -> bf16x2 smem
    for (int k = tid; k < 32 * HH; k += 256) {
        const int p = k >> 8, h = k & 255;
        WgB[p * WGB + h] = bfx2(Wg[(2 * p) * HH + h], Wg[(2 * p + 1) * HH + h]);
    }

    // prologue dots: warp (z*2 + sel): c1 (u) / s0 (v)
    {
        const int z = warp >> 1;
        const float* src = (warp & 1) ? (g_v + z * HH) : (g_u + z * HH);
        float s = 0.f;
        #pragma unroll
        for (int h = lane; h < HH; h += 32) s = fmaf(ahs[i * HH + h], src[h], s);
        #pragma unroll
        for (int o = 16; o; o >>= 1) s += __shfl_xor_sync(0xffffffffu, s, o);
        if (lane == 0) cvec[(warp & 1) * 4 + z] = s;
    }

    // preload per-thread v pairs (4 heads x 4 ntiles) and gate-bias pairs
    float2 v2[NHD][4], bg2[4];
    #pragma unroll
    for (int nt = 0; nt < 4; nt++) {
        const int hb = warp * 32 + nt * 8 + 2 * T;
        bg2[nt] = *(const float2*)&bg[hb];
        #pragma unroll
        for (int z = 0; z < NHD; z++)
            v2[z][nt] = *(const float2*)&g_v[z * HH + hb];
    }

    const float ahs_i = ahs[i * HH + tid];

    // qsB prefill helper (parameterized thread range)
    auto prefill = [&](int jn0, int t0, int stride) {
        for (int idx = t0; idx < 32 * CHUNK; idx += stride) {
            const int p = idx >> 5, jj = idx & 31;
            const float v0 = fmaxf(g_C[i * DDE + 2 * p]     + g_PT[(2 * p) * NN + jn0 + jj], 0.f);
            const float v1 = fmaxf(g_C[i * DDE + 2 * p + 1] + g_PT[(2 * p + 1) * NN + jn0 + jj], 0.f);
            qsB[jj * QSB + p] = bfx2(v0, v1);
        }
    };

    // GEMM + epilogue for chunk cc, writing gh buffer gho and spp
    auto gemm_epi = [&](int cc, float* gho) {
        const int j0 = cc * CHUNK;
        // hoisted tanh-table loads (hide L2 under GEMM)
        float2 tj[4][4];
        #pragma unroll
        for (int mt = 0; mt < 2; mt++) {
            const int ja = j0 + mt * 16 + g, jb = ja + 8;
            #pragma unroll
            for (int nt = 0; nt < 4; nt++) {
                const int hb = warp * 32 + nt * 8 + 2 * T;
                tj[mt * 2 + 0][nt] = *(const float2*)&g_tTj[ja * HH + hb];
                tj[mt * 2 + 1][nt] = *(const float2*)&g_tTj[jb * HH + hb];
            }
        }
        float acc[2][4][4];
        #pragma unroll
        for (int mt = 0; mt < 2; mt++)
            #pragma unroll
            for (int nt = 0; nt < 4; nt++)
                #pragma unroll
                for (int e = 0; e < 4; e++) acc[mt][nt][e] = 0.f;
        #pragma unroll
        for (int kt = 0; kt < 4; kt++) {
            unsigned a[2][4], b[4][2];
            #pragma unroll
            for (int mt = 0; mt < 2; mt++) {
                const int ra = (mt * 16 + g) * QSB + kt * 8 + T;
                const int rb = ra + 8 * QSB;
                a[mt][0] = qsB[ra];
                a[mt][1] = qsB[rb];
                a[mt][2] = qsB[ra + 4];
                a[mt][3] = qsB[rb + 4];
            }
            #pragma unroll
            for (int nt = 0; nt < 4; nt++) {
                const int bi = (kt * 8 + T) * WGB + warp * 32 + nt * 8 + g;
                b[nt][0] = WgB[bi];
                b[nt][1] = WgB[bi + 4 * WGB];
            }
            #pragma unroll
            for (int mt = 0; mt < 2; mt++)
                #pragma unroll
                for (int nt = 0; nt < 4; nt++)
                    mma_bf16(acc[mt][nt], a[mt], b[nt]);
        }
        // epilogue: bias + sigmoid*tanh (diag override), store gh, fused scores
        float p[4][4];
        #pragma unroll
        for (int r = 0; r < 4; r++)
            #pragma unroll
            for (int z = 0; z < 4; z++) p[r][z] = 0.f;
        #pragma unroll
        for (int mt = 0; mt < 2; mt++) {
            const int ja = j0 + mt * 16 + g;
            const int jb = ja + 8;
            #pragma unroll
            for (int nt = 0; nt < 4; nt++) {
                const int hb = warp * 32 + nt * 8 + 2 * T;
                const float x00 = acc[mt][nt][0] + bg2[nt].x;
                const float x01 = acc[mt][nt][1] + bg2[nt].y;
                const float x10 = acc[mt][nt][2] + bg2[nt].x;
                const float x11 = acc[mt][nt][3] + bg2[nt].y;
                float2 gva, gvb;
                if (ja == i) {
                    gva = *(const float2*)&ghs[i * HH + hb];
                } else {
                    const float2 t = tj[mt * 2 + 0][nt];
                    gva.x = sig_ap(x00) * t.x;
                    gva.y = sig_ap(x01) * t.y;
                }
                if (jb == i) {
                    gvb = *(const float2*)&ghs[i * HH + hb];
                } else {
                    const float2 t = tj[mt * 2 + 1][nt];
                    gvb.x = sig_ap(x10) * t.x;
                    gvb.y = sig_ap(x11) * t.y;
                }
                *(float2*)&gho[(mt * 16 + g) * GH + hb]     = gva;
                *(float2*)&gho[(mt * 16 + g + 8) * GH + hb] = gvb;
                #pragma unroll
                for (int z = 0; z < 4; z++) {
                    p[mt * 2 + 0][z] = fmaf(gva.x, v2[z][nt].x,
                                       fmaf(gva.y, v2[z][nt].y, p[mt * 2 + 0][z]));
                    p[mt * 2 + 1][z] = fmaf(gvb.x, v2[z][nt].x,
                                       fmaf(gvb.y, v2[z][nt].y, p[mt * 2 + 1][z]));
                }
            }
        }
        // transpose-reduce over the quad: lane T ends with sum_{quad} p[r][z=T]
        const bool t1 = (T & 1), t2 = (T & 2);
        #pragma unroll
        for (int r = 0; r < 4; r++) {
            float k0 = t1 ? p[r][1] : p[r][0];
            float s0 = t1 ? p[r][0] : p[r][1];
            float k2 = t1 ? p[r][3] : p[r][2];
            float s2 = t1 ? p[r][2] : p[r][3];
            k0 += __shfl_xor_sync(0xffffffffu, s0, 1);
            k2 += __shfl_xor_sync(0xffffffffu, s2, 1);
            float kk = t2 ? k2 : k0;
            float ss = t2 ? k0 : k2;
            kk += __shfl_xor_sync(0xffffffffu, ss, 2);
            spp[T * 256 + (r * 8 + g) * 8 + warp] = kk;
        }
    };

    __syncthreads();   // WgB + cvec ready

    // online-softmax state (replicated across threads)
    float runmax0, runmax1, runmax2, runmax3;
    float denom0 = 1.f, denom1 = 1.f, denom2 = 1.f, denom3 = 1.f;
    {
        const float s0v = cvec[0] + cvec[4], s1v = cvec[1] + cvec[5];
        const float s2v = cvec[2] + cvec[6], s3v = cvec[3] + cvec[7];
        runmax0 = (s0v > 0.f) ? s0v : 0.2f * s0v;
        runmax1 = (s1v > 0.f) ? s1v : 0.2f * s1v;
        runmax2 = (s2v > 0.f) ? s2v : 0.2f * s2v;
        runmax3 = (s3v > 0.f) ? s3v : 0.2f * s3v;
    }
    ull mA = pk2(ahs_i, ahs_i), mB = mA;   // (m0,m1),(m2,m3)

    // prologue: chunk 0 qs + GEMM/epilogue
    prefill(0, tid, 256);
    __syncthreads();
    gemm_epi(0, ghbuf);
    __syncthreads();   // A(0): gh[0] + spp(0) ready

    for (int c = 0; c < NCHUNK; c++) {
        // ---- phase 1: warps 0-3 softmax(c); warps 4-7 prefill qsB(c+1) ----
        if (warp < 4) {
            const float4 ea = *(const float4*)&spp[warp * 256 + lane * 8];
            const float4 eb = *(const float4*)&spp[warp * 256 + lane * 8 + 4];
            float e = cvec[warp] + ((ea.x + ea.y) + (ea.z + ea.w))
                                 + ((eb.x + eb.y) + (eb.z + eb.w));
            e = (e > 0.f) ? e : 0.2f * e;
            const float rmz = (warp == 0) ? runmax0 : (warp == 1) ? runmax1
                            : (warp == 2) ? runmax2 : runmax3;
            float mx = e;
            #pragma unroll
            for (int o = 16; o; o >>= 1) mx = fmaxf(mx, __shfl_xor_sync(0xffffffffu, mx, o));
            const float nm = fmaxf(rmz, mx);
            const float pp = __expf(e - nm);
            psh[lane * 4 + warp] = pp;
            float ps = pp;
            #pragma unroll
            for (int o = 16; o; o >>= 1) ps += __shfl_xor_sync(0xffffffffu, ps, o);
            if (lane == 0) { bc[warp] = mx; bc[4 + warp] = ps; }
        } else if (c + 1 < NCHUNK) {
            prefill((c + 1) * CHUNK, tid - 128, 128);
        }
        __syncthreads();   // B: psh + bc + next qsB ready

        // ---- phase 2: merge state + m-accum(c), then GEMM/epilogue(c+1) ----
        {
            const float nm0 = fmaxf(runmax0, bc[0]);
            const float nm1 = fmaxf(runmax1, bc[1]);
            const float nm2 = fmaxf(runmax2, bc[2]);
            const float nm3 = fmaxf(runmax3, bc[3]);
            const float s0 = __expf(runmax0 - nm0), s1 = __expf(runmax1 - nm1);
            const float s2 = __expf(runmax2 - nm2), s3 = __expf(runmax3 - nm3);
            denom0 = denom0 * s0 + bc[4]; denom1 = denom1 * s1 + bc[5];
            denom2 = denom2 * s2 + bc[6]; denom3 = denom3 * s3 + bc[7];
            runmax0 = nm0; runmax1 = nm1; runmax2 = nm2; runmax3 = nm3;
            mA = mul2_(mA, pk2(s0, s1));
            mB = mul2_(mB, pk2(s2, s3));
        }
        {
            const float* ghc = ghbuf + (c & 1) * CHUNK * GH;
            #pragma unroll 4
            for (int jj = 0; jj < CHUNK; jj++) {
                const float ghv = ghc[jj * GH + tid];
                const ulonglong2 pp = *(const ulonglong2*)&psh[jj * 4];
                const ull gd = pk2(ghv, ghv);
                mA = fma2_(pp.x, gd, mA);
                mB = fma2_(pp.y, gd, mB);
            }
        }
        if (c + 1 < NCHUNK) {
            gemm_epi(c + 1, ghbuf + ((c + 1) & 1) * CHUNK * GH);
            __syncthreads();   // A(c+1): gh[(c+1)&1] + spp(c+1) ready
        }
    }

    // write normalized m: g_msm[i][z*256 + h]
    {
        const float2 fA = upk2(mA), fB = upk2(mB);
        g_msm[i * (NHD * HH) + 0 * HH + tid] = fA.x / denom0;
        g_msm[i * (NHD * HH) + 1 * HH + tid] = fA.y / denom1;
        g_msm[i * (NHD * HH) + 2 * HH + tid] = fB.x / denom2;
        g_msm[i * (NHD * HH) + 3 * HH + tid] = fB.y / denom3;
    }
}

// ---------------- projection kernel: coalesced gather, stride-12 smem ----------------
#define MS 12   // msm_s row stride (floats): 4-way fill conflict, 16B-aligned reads
__global__ void __launch_bounds__(512) projK(const float* __restrict__ w,
                                             const float* __restrict__ bias,
                                             float* __restrict__ out) {
    __shared__ float msm_s[1024 * MS];   // [k][n] stride 12
    __shared__ float sacc[4096];         // [kw(16)][n(8)][fl(32)]
    const int tid = threadIdx.x;
    const int f0 = (blockIdx.x & 7) * 32;
    const int n0 = (blockIdx.x >> 3) * 8;

    // coalesced: consecutive threads read consecutive k of the same n row
    for (int idx = tid; idx < 8192; idx += 512) {
        const int n = idx >> 10, k = idx & 1023;
        msm_s[k * MS + n] = g_msm[(n0 + n) * 1024 + k];
    }
    __syncthreads();

    const int fl = tid & 31, kw = tid >> 5;   // kw 0..15
    float acc[8] = {0.f, 0.f, 0.f, 0.f, 0.f, 0.f, 0.f, 0.f};
    const float* wp = w + f0 + fl;
    const int kbeg = kw * 64;
    #pragma unroll 8
    for (int k = kbeg; k < kbeg + 64; k++) {
        const float wv = wp[k * 256];
        const float4 ma = *(const float4*)&msm_s[k * MS];
        const float4 mb = *(const float4*)&msm_s[k * MS + 4];
        acc[0] = fmaf(wv, ma.x, acc[0]); acc[1] = fmaf(wv, ma.y, acc[1]);
        acc[2] = fmaf(wv, ma.z, acc[2]); acc[3] = fmaf(wv, ma.w, acc[3]);
        acc[4] = fmaf(wv, mb.x, acc[4]); acc[5] = fmaf(wv, mb.y, acc[5]);
        acc[6] = fmaf(wv, mb.z, acc[6]); acc[7] = fmaf(wv, mb.w, acc[7]);
    }
    #pragma unroll
    for (int n = 0; n < 8; n++) sacc[(kw * 8 + n) * 32 + fl] = acc[n];
    __syncthreads();

    if (tid < 256) {
        const int n = tid >> 5;
        float s = 0.f;
        #pragma unroll
        for (int k2 = 0; k2 < 16; k2++) s += sacc[(k2 * 8 + n) * 32 + fl];
        out[(n0 + n) * 256 + f0 + fl] = fmaxf(0.25f * s, 0.f) + bias[f0 + fl];
    }
}

// ---------------- launch ----------------
extern "C" void kernel_launch(void* const* d_in, const int* in_sizes, int n_in,
                              void* d_out, int out_size) {
    (void)in_sizes; (void)n_in; (void)out_size;
    const float* ahs    = (const float*)d_in[0];
    const float* ghs    = (const float*)d_in[1];
    const float* goal   = (const float*)d_in[2];
    const float* action = (const float*)d_in[3];
    const float* Wd     = (const float*)d_in[4];
    const float* bd     = (const float*)d_in[5];
    const float* Wg     = (const float*)d_in[6];
    const float* bg     = (const float*)d_in[7];
    const float* w      = (const float*)d_in[8];
    const float* a      = (const float*)d_in[9];
    const float* bias   = (const float*)d_in[10];
    float* out = (float*)d_out;

    cudaFuncSetAttribute(mainK, cudaFuncAttributeMaxDynamicSharedMemorySize, SM_BYTES);

    prepK<<<NN + 128, 256>>>(ahs, goal, action, Wd, bd, w, a);
    mainK<<<NN, 256, SM_BYTES>>>(ahs, ghs, Wg, bg);
    projK<<<NN, 512>>>(w, bias, out);
}